// round 4
// baseline (speedup 1.0000x reference)
#include <cuda_runtime.h>

// Problem constants (fixed by reference_code)
#define NN    48000     // total nodes
#define BB    16        // graphs
#define NPG   3000      // nodes per graph
#define EE    800000    // edges
#define DD    128       // feature dim (all layers)
#define KK    16        // base nodes per graph
#define DCOND 32
#define NC    2

// ---------------- device scratch (static, no runtime allocation) ----------------
__device__ float g_bufA[NN * DD];     // 24.6 MB
__device__ float g_bufB[NN * DD];     // 24.6 MB
__device__ int   g_cnt[NN];           // in-degree histogram
__device__ int   g_off[NN + 1];       // CSR row offsets (by dst)
__device__ int   g_cur[NN];           // scatter cursors
__device__ int   g_csrc[EE];          // CSR src indices
__device__ float g_cnorm[EE];         // per-edge norm = isq[src]*isq[dst]
__device__ float g_isq[NN];           // deg^{-1/2} (deg includes self loop)
__device__ float g_xg[BB * DD];       // global mean pool
__device__ float g_z1[BB * DD];       // lin1 accumulator

// ---------------- CSR build ----------------
__global__ void k_zero() {
    int i = blockIdx.x * blockDim.x + threadIdx.x;
    if (i < NN) g_cnt[i] = 0;
    if (i < BB * DD) g_z1[i] = 0.f;
}

__global__ void k_hist(const int* __restrict__ dst) {
    int e = blockIdx.x * 256 + threadIdx.x;
    if (e < EE) atomicAdd(&g_cnt[dst[e]], 1);
}

// Single-block exclusive scan over 48000 counts (1024 threads x 47 elems)
__global__ void k_scan() {
    __shared__ int sh[1024];
    const int CH = 47;
    int t = threadIdx.x;
    int base = t * CH;
    int s = 0;
    for (int i = 0; i < CH; i++) {
        int idx = base + i;
        if (idx < NN) s += g_cnt[idx];
    }
    sh[t] = s;
    __syncthreads();
    for (int d = 1; d < 1024; d <<= 1) {
        int v = (t >= d) ? sh[t - d] : 0;
        __syncthreads();
        sh[t] += v;
        __syncthreads();
    }
    int run = (t > 0) ? sh[t - 1] : 0;
    for (int i = 0; i < CH; i++) {
        int idx = base + i;
        if (idx < NN) {
            int c = g_cnt[idx];
            g_off[idx] = run;
            g_cur[idx] = run;
            g_isq[idx] = rsqrtf((float)c + 1.0f);   // deg = in-deg + self loop
            run += c;
        }
    }
    if (t == 1023) g_off[NN] = run;   // == EE
}

__global__ void k_scatter(const int* __restrict__ src, const int* __restrict__ dst) {
    int e = blockIdx.x * 256 + threadIdx.x;
    if (e < EE) {
        int s = src[e], d = dst[e];
        int p = atomicAdd(&g_cur[d], 1);
        g_csrc[p] = s;
        g_cnorm[p] = g_isq[s] * g_isq[d];
    }
}

// ---------------- GEMM: C[48000,128] = A[48000,128] @ W[128,128] ----------------
// Block: 128 rows x 128 cols, 256 threads, 8x8 register micro-tile.
// W and A tile fully staged in 128 KB dynamic SMEM. FMA-pipe bound by design.
__global__ void k_gemm(const float* __restrict__ A, const float* __restrict__ W,
                       float* __restrict__ C) {
    extern __shared__ float sh[];
    float* Ws = sh;               // 128*128
    float* As = sh + DD * DD;     // 128*128
    int tid = threadIdx.x;
    int row0 = blockIdx.x * 128;

    const float4* W4 = (const float4*)W;
    const float4* A4 = (const float4*)(A + (size_t)row0 * DD);
    float4* Ws4 = (float4*)Ws;
    float4* As4 = (float4*)As;
#pragma unroll
    for (int i = 0; i < 16; i++) {
        Ws4[tid + 256 * i] = W4[tid + 256 * i];
        As4[tid + 256 * i] = A4[tid + 256 * i];
    }
    __syncthreads();

    int tcol = tid & 15;          // 16 col-groups of 8
    int trow = tid >> 4;          // 16 row-groups of 8
    float acc[8][8];
#pragma unroll
    for (int r = 0; r < 8; r++)
#pragma unroll
        for (int c = 0; c < 8; c++) acc[r][c] = 0.f;

#pragma unroll 4
    for (int k = 0; k < DD; k++) {
        float a[8];
#pragma unroll
        for (int r = 0; r < 8; r++) a[r] = As[(trow * 8 + r) * DD + k];
        float4 w0 = *(const float4*)&Ws[k * DD + tcol * 8];
        float4 w1 = *(const float4*)&Ws[k * DD + tcol * 8 + 4];
        float w[8] = {w0.x, w0.y, w0.z, w0.w, w1.x, w1.y, w1.z, w1.w};
#pragma unroll
        for (int r = 0; r < 8; r++)
#pragma unroll
            for (int c = 0; c < 8; c++) acc[r][c] = fmaf(a[r], w[c], acc[r][c]);
    }

#pragma unroll
    for (int r = 0; r < 8; r++) {
        float4* o = (float4*)&C[(size_t)(row0 + trow * 8 + r) * DD + tcol * 8];
        o[0] = make_float4(acc[r][0], acc[r][1], acc[r][2], acc[r][3]);
        o[1] = make_float4(acc[r][4], acc[r][5], acc[r][6], acc[r][7]);
    }
}

// ---------------- Aggregation: warp per dst node, atomic-free CSR gather ----------------
// out[d] = sum_e hw[src_e]*norm_e + hw[d]*isq[d]^2 + bias ; optional ReLU
__global__ void k_agg(const float* __restrict__ HW, float* __restrict__ OUT,
                      const float* __restrict__ bias, int do_relu) {
    int warp = threadIdx.x >> 5;
    int lane = threadIdx.x & 31;
    int node = blockIdx.x * 4 + warp;

    const float4* hw4 = (const float4*)HW;
    float isqd = g_isq[node];
    float sc = isqd * isqd;
    float4 acc = hw4[node * 32 + lane];
    acc.x *= sc; acc.y *= sc; acc.z *= sc; acc.w *= sc;

    int e0 = g_off[node], e1 = g_off[node + 1];
    for (int e = e0; e < e1; e += 32) {
        int m = min(32, e1 - e);
        int s = 0; float nn = 0.f;
        if (lane < m) { s = g_csrc[e + lane]; nn = g_cnorm[e + lane]; }
        for (int j = 0; j < m; j++) {
            int   ss = __shfl_sync(0xffffffffu, s, j);
            float w  = __shfl_sync(0xffffffffu, nn, j);
            float4 v = hw4[ss * 32 + lane];
            acc.x = fmaf(v.x, w, acc.x);
            acc.y = fmaf(v.y, w, acc.y);
            acc.z = fmaf(v.z, w, acc.z);
            acc.w = fmaf(v.w, w, acc.w);
        }
    }
    float4 bv = ((const float4*)bias)[lane];
    acc.x += bv.x; acc.y += bv.y; acc.z += bv.z; acc.w += bv.w;
    if (do_relu) {
        acc.x = fmaxf(acc.x, 0.f); acc.y = fmaxf(acc.y, 0.f);
        acc.z = fmaxf(acc.z, 0.f); acc.w = fmaxf(acc.w, 0.f);
    }
    ((float4*)OUT)[node * 32 + lane] = acc;
}

// ---------------- Global mean pool: one block per graph ----------------
__global__ void k_pool(const float* __restrict__ H) {
    int g = blockIdx.x, t = threadIdx.x;
    const float* p = H + (size_t)g * NPG * DD + t;
    float s = 0.f;
#pragma unroll 4
    for (int i = 0; i < NPG; i++) s += p[(size_t)i * DD];
    g_xg[g * DD + t] = s * (1.0f / NPG);
}

// ---------------- lin1: z[16,2176] @ W[2176,128], split over i-dimension ----------------
__global__ void k_lin1(const float* __restrict__ H, const int* __restrict__ base,
                       const float* __restrict__ W1) {
    __shared__ float zsh[BB * 128];   // this block's z slice
    int t = threadIdx.x;
    int i0 = blockIdx.x * 128;        // 17 blocks cover i in [0,2176)

    for (int idx = t; idx < BB * 128; idx += 128) {
        int g = idx >> 7, ii = idx & 127;
        int i = i0 + ii;
        float v;
        if (i < KK * DD) {            // selective gather part x_s
            int k = i >> 7, d = i & 127;
            int bn = base[g * KK + k];
            v = (bn > 0) ? H[((size_t)g * NPG + bn) * DD + d] : 0.f;
        } else {                      // global pool part x_g
            v = g_xg[g * DD + (i - KK * DD)];
        }
        zsh[idx] = v;
    }
    __syncthreads();

    float acc[BB];
#pragma unroll
    for (int g = 0; g < BB; g++) acc[g] = 0.f;
    for (int ii = 0; ii < 128; ii++) {
        float w = W1[(size_t)(i0 + ii) * DD + t];
#pragma unroll
        for (int g = 0; g < BB; g++) acc[g] = fmaf(zsh[g * 128 + ii], w, acc[g]);
    }
#pragma unroll
    for (int g = 0; g < BB; g++) atomicAdd(&g_z1[g * DD + t], acc[g]);
}

// ---------------- final: relu(z1 + b) concat cond -> lin2 -> out[16,2] ----------------
__global__ void k_final(const float* __restrict__ lin1_b, const float* __restrict__ cond,
                        const float* __restrict__ W2, const float* __restrict__ b2,
                        float* __restrict__ out) {
    int t = threadIdx.x;
    if (t >= BB * NC) return;
    int g = t >> 1, c = t & 1;
    float acc = b2[c];
    for (int j = 0; j < DD; j++) {
        float z = fmaxf(g_z1[g * DD + j] + lin1_b[j], 0.f);
        acc = fmaf(z, W2[j * NC + c], acc);
    }
    for (int j = 0; j < DCOND; j++)
        acc = fmaf(cond[g * DCOND + j], W2[(DD + j) * NC + c], acc);
    out[g * NC + c] = acc;
}

// ---------------- launch ----------------
extern "C" void kernel_launch(void* const* d_in, const int* in_sizes, int n_in,
                              void* d_out, int out_size) {
    const float* x      = (const float*)d_in[0];
    const int*   ei     = (const int*)d_in[1];
    const int*   src    = ei;
    const int*   dst    = ei + EE;
    const int*   base   = (const int*)d_in[3];
    const float* cond   = (const float*)d_in[4];
    const float* W[5]   = {(const float*)d_in[5], (const float*)d_in[7],
                           (const float*)d_in[9], (const float*)d_in[11],
                           (const float*)d_in[13]};
    const float* bias[5] = {(const float*)d_in[6], (const float*)d_in[8],
                            (const float*)d_in[10], (const float*)d_in[12],
                            (const float*)d_in[14]};
    const float* lin1_W = (const float*)d_in[15];
    const float* lin1_b = (const float*)d_in[16];
    const float* lin2_W = (const float*)d_in[17];
    const float* lin2_b = (const float*)d_in[18];
    float* out = (float*)d_out;

    // 128 KB dynamic SMEM for the GEMM (idempotent; not a stream op, capture-safe)
    cudaFuncSetAttribute(k_gemm, cudaFuncAttributeMaxDynamicSharedMemorySize, 131072);

    void *pa, *pb;
    cudaGetSymbolAddress(&pa, g_bufA);
    cudaGetSymbolAddress(&pb, g_bufB);
    float* A  = (float*)pa;
    float* Bv = (float*)pb;

    // CSR build (recomputed every launch; deterministic work)
    k_zero<<<(NN + 255) / 256, 256>>>();
    k_hist<<<EE / 256, 256>>>(dst);
    k_scan<<<1, 1024>>>();
    k_scatter<<<EE / 256, 256>>>(src, dst);

    // 5 GCN layers (ping-pong between g_bufA / g_bufB)
    k_gemm<<<NN / 128, 256, 131072>>>(x, W[0], Bv);
    k_agg<<<NN / 4, 128>>>(Bv, A, bias[0], 1);
    for (int l = 1; l < 5; l++) {
        k_gemm<<<NN / 128, 256, 131072>>>(A, W[l], Bv);
        k_agg<<<NN / 4, 128>>>(Bv, A, bias[l], (l < 4) ? 1 : 0);
    }

    // readout
    k_pool<<<BB, 128>>>(A);
    k_lin1<<<17, 128>>>(A, base, lin1_W);
    k_final<<<1, 32>>>(lin1_b, cond, lin2_W, lin2_b, out);
}

// round 6
// speedup vs baseline: 1.3077x; 1.3077x over previous
#include <cuda_runtime.h>

// Problem constants (fixed by reference_code)
#define NN    48000     // total nodes
#define BB    16        // graphs
#define NPG   3000      // nodes per graph
#define EE    800000    // edges
#define DD    128       // feature dim (all layers)
#define KK    16        // base nodes per graph
#define DCOND 32
#define NC    2

#define NBLK  188       // ceil(NN/256)

// ---------------- device scratch (static, no runtime allocation) ----------------
__device__ float g_bufA[NN * DD];     // 24.6 MB
__device__ float g_bufB[NN * DD];     // 24.6 MB
__device__ int   g_cnt[NN];           // in-degree histogram
__device__ int   g_off[NN + 1];       // CSR row offsets (by dst)
__device__ int   g_cur[NN];           // scatter cursors
__device__ int   g_csrc[EE];          // CSR src indices
__device__ float g_isq[NN];           // deg^{-1/2} (deg includes self loop)
__device__ int   g_part[NBLK];        // scan partials
__device__ float g_xg[BB * DD];       // global mean pool
__device__ float g_z1[BB * DD];       // lin1 accumulator

// ---------------- f32x2 helpers (packed fp32 pair ops, sm_100+) ----------------
typedef unsigned long long u64t;

__device__ __forceinline__ u64t pk2(float lo, float hi) {
    u64t r; asm("mov.b64 %0, {%1, %2};" : "=l"(r) : "f"(lo), "f"(hi)); return r;
}
__device__ __forceinline__ u64t pkb(float x) {   // broadcast pack
    u64t r; asm("mov.b64 %0, {%1, %1};" : "=l"(r) : "f"(x)); return r;
}
__device__ __forceinline__ void unpk2(u64t v, float& lo, float& hi) {
    asm("mov.b64 {%0, %1}, %2;" : "=f"(lo), "=f"(hi) : "l"(v));
}
__device__ __forceinline__ void ffma2(u64t& d, u64t a, u64t b) {
    asm("fma.rn.f32x2 %0, %1, %2, %0;" : "+l"(d) : "l"(a), "l"(b));
}
__device__ __forceinline__ u64t fadd2(u64t a, u64t b) {
    u64t r; asm("add.rn.f32x2 %0, %1, %2;" : "=l"(r) : "l"(a), "l"(b)); return r;
}

// ---------------- init ----------------
__global__ void k_zero() {
    int i = blockIdx.x * blockDim.x + threadIdx.x;
    if (i < NN) g_cnt[i] = 0;
    if (i < BB * DD) { g_z1[i] = 0.f; g_xg[i] = 0.f; }
}

__global__ void k_hist(const int* __restrict__ dst) {
    int e = blockIdx.x * 256 + threadIdx.x;
    if (e < EE) atomicAdd(&g_cnt[dst[e]], 1);
}

// ---------------- 3-phase parallel scan ----------------
__global__ void k_scan1() {   // per-block sums + isq
    __shared__ int sh[256];
    int t = threadIdx.x;
    int i = blockIdx.x * 256 + t;
    int c = (i < NN) ? g_cnt[i] : 0;
    if (i < NN) g_isq[i] = rsqrtf((float)c + 1.0f);
    sh[t] = c;
    __syncthreads();
    for (int d = 128; d > 0; d >>= 1) {
        if (t < d) sh[t] += sh[t + d];
        __syncthreads();
    }
    if (t == 0) g_part[blockIdx.x] = sh[0];
}

__global__ void k_scan2() {   // exclusive scan of 188 partials
    __shared__ int sh[256];
    int t = threadIdx.x;
    int v = (t < NBLK) ? g_part[t] : 0;
    sh[t] = v;
    __syncthreads();
    for (int d = 1; d < 256; d <<= 1) {
        int x = (t >= d) ? sh[t - d] : 0;
        __syncthreads();
        sh[t] += x;
        __syncthreads();
    }
    if (t < NBLK) g_part[t] = sh[t] - v;   // exclusive
}

__global__ void k_scan3() {   // per-block exclusive scan + global offset
    __shared__ int sh[256];
    int t = threadIdx.x;
    int i = blockIdx.x * 256 + t;
    int c = (i < NN) ? g_cnt[i] : 0;
    sh[t] = c;
    __syncthreads();
    for (int d = 1; d < 256; d <<= 1) {
        int x = (t >= d) ? sh[t - d] : 0;
        __syncthreads();
        sh[t] += x;
        __syncthreads();
    }
    if (i < NN) {
        int off = g_part[blockIdx.x] + sh[t] - c;
        g_off[i] = off;
        g_cur[i] = off;
    }
    if (blockIdx.x == 0 && t == 0) g_off[NN] = EE;
}

__global__ void k_scatter(const int* __restrict__ src, const int* __restrict__ dst) {
    int e = blockIdx.x * 256 + threadIdx.x;
    if (e < EE) {
        int d = dst[e];
        int p = atomicAdd(&g_cur[d], 1);
        g_csrc[p] = src[e];
    }
}

// ---------------- GEMM: C[48000,128] = A[48000,128] @ W[128,128] ----------------
// 64-row x 128-col tile, 256 threads, 4x8 register micro-tile via packed f32x2.
// 96 KB smem -> 2 blocks/SM. FFMA2-pipe bound (2x scalar FFMA rate).
__global__ void __launch_bounds__(256, 2) k_gemm(const float* __restrict__ A,
                                                 const float* __restrict__ W,
                                                 float* __restrict__ C) {
    extern __shared__ float sh[];
    float* Ws = sh;               // 128*128 = 64 KB
    float* As = sh + DD * DD;     // 64*128  = 32 KB
    int tid = threadIdx.x;
    int row0 = blockIdx.x * 64;

    {   // stage W (4096 float4) and A tile (2048 float4)
        const float4* W4 = (const float4*)W;
        const float4* A4 = (const float4*)(A + (size_t)row0 * DD);
        float4* Ws4 = (float4*)Ws;
        float4* As4 = (float4*)As;
#pragma unroll
        for (int i = 0; i < 16; i++) Ws4[tid + 256 * i] = W4[tid + 256 * i];
#pragma unroll
        for (int i = 0; i < 8; i++)  As4[tid + 256 * i] = A4[tid + 256 * i];
    }
    __syncthreads();

    int tcol = tid & 15;          // 16 col-groups of 8
    int trow = tid >> 4;          // 16 row-groups of 4
    u64t acc[4][4];               // 4 rows x 4 col-pairs (8 cols)
#pragma unroll
    for (int r = 0; r < 4; r++)
#pragma unroll
        for (int c = 0; c < 4; c++) acc[r][c] = 0ull;

    const float* a_base = &As[(trow * 4) * DD];
    const float* w_base = &Ws[tcol * 8];

#pragma unroll 4
    for (int k4 = 0; k4 < DD; k4 += 4) {
        float4 a4[4];
#pragma unroll
        for (int r = 0; r < 4; r++)
            a4[r] = *(const float4*)(a_base + r * DD + k4);
#pragma unroll
        for (int kk = 0; kk < 4; kk++) {
            const float4* wp = (const float4*)(w_base + (k4 + kk) * DD);
            float4 w0 = wp[0];
            float4 w1 = wp[1];
            u64t wv[4];
            wv[0] = pk2(w0.x, w0.y); wv[1] = pk2(w0.z, w0.w);
            wv[2] = pk2(w1.x, w1.y); wv[3] = pk2(w1.z, w1.w);
#pragma unroll
            for (int r = 0; r < 4; r++) {
                float av = (kk == 0) ? a4[r].x : (kk == 1) ? a4[r].y
                         : (kk == 2) ? a4[r].z : a4[r].w;
                u64t ab = pkb(av);
#pragma unroll
                for (int c = 0; c < 4; c++) ffma2(acc[r][c], ab, wv[c]);
            }
        }
    }

#pragma unroll
    for (int r = 0; r < 4; r++) {
        float o[8];
#pragma unroll
        for (int c = 0; c < 4; c++) unpk2(acc[r][c], o[2 * c], o[2 * c + 1]);
        float4* out = (float4*)&C[(size_t)(row0 + trow * 4 + r) * DD + tcol * 8];
        out[0] = make_float4(o[0], o[1], o[2], o[3]);
        out[1] = make_float4(o[4], o[5], o[6], o[7]);
    }
}

// ---------------- Aggregation: warp per dst node, atomic-free CSR gather ----------------
// out[d] = sum_e hw[src_e]*isq[s]*isq[d] + hw[d]*isq[d]^2 + bias ; optional ReLU
__global__ void __launch_bounds__(128) k_agg(const float* __restrict__ HW,
                                             float* __restrict__ OUT,
                                             const float* __restrict__ bias, int do_relu) {
    int warp = threadIdx.x >> 5;
    int lane = threadIdx.x & 31;
    int node = blockIdx.x * 4 + warp;

    const ulonglong2* hw2 = (const ulonglong2*)HW;
    float isqd = g_isq[node];
    float sc = isqd * isqd;

    // self-loop term
    float4 self = ((const float4*)HW)[node * 32 + lane];
    u64t acc0a = pk2(self.x * sc, self.y * sc);
    u64t acc0b = pk2(self.z * sc, self.w * sc);
    u64t acc1a = 0ull, acc1b = 0ull;

    int e0 = g_off[node], e1 = g_off[node + 1];
    for (int e = e0; e < e1; e += 32) {
        int m = min(32, e1 - e);
        int s = 0; float nn = 0.f;
        if (lane < m) {
            s = g_csrc[e + lane];
            nn = g_isq[s] * isqd;       // g_isq slice is L1-resident (12 KB/graph)
        }
        int j = 0;
        for (; j + 1 < m; j += 2) {
            int   s0 = __shfl_sync(0xffffffffu, s, j);
            int   s1 = __shfl_sync(0xffffffffu, s, j + 1);
            float w0 = __shfl_sync(0xffffffffu, nn, j);
            float w1 = __shfl_sync(0xffffffffu, nn, j + 1);
            ulonglong2 v0 = hw2[s0 * 32 + lane];
            ulonglong2 v1 = hw2[s1 * 32 + lane];
            u64t wb0 = pkb(w0), wb1 = pkb(w1);
            ffma2(acc0a, v0.x, wb0); ffma2(acc0b, v0.y, wb0);
            ffma2(acc1a, v1.x, wb1); ffma2(acc1b, v1.y, wb1);
        }
        if (j < m) {
            int   s0 = __shfl_sync(0xffffffffu, s, j);
            float w0 = __shfl_sync(0xffffffffu, nn, j);
            ulonglong2 v0 = hw2[s0 * 32 + lane];
            u64t wb0 = pkb(w0);
            ffma2(acc0a, v0.x, wb0); ffma2(acc0b, v0.y, wb0);
        }
    }
    u64t ra = fadd2(acc0a, acc1a);
    u64t rb = fadd2(acc0b, acc1b);
    float4 r;
    unpk2(ra, r.x, r.y);
    unpk2(rb, r.z, r.w);
    float4 bv = ((const float4*)bias)[lane];
    r.x += bv.x; r.y += bv.y; r.z += bv.z; r.w += bv.w;
    if (do_relu) {
        r.x = fmaxf(r.x, 0.f); r.y = fmaxf(r.y, 0.f);
        r.z = fmaxf(r.z, 0.f); r.w = fmaxf(r.w, 0.f);
    }
    ((float4*)OUT)[node * 32 + lane] = r;
}

// ---------------- Global mean pool: 16 graphs x 8 chunks ----------------
__global__ void k_pool(const float* __restrict__ H) {
    int g = blockIdx.x, ch = blockIdx.y, t = threadIdx.x;
    const float* p = H + ((size_t)g * NPG + ch * (NPG / 8)) * DD + t;
    float s = 0.f;
#pragma unroll 5
    for (int i = 0; i < NPG / 8; i++) s += p[(size_t)i * DD];
    atomicAdd(&g_xg[g * DD + t], s * (1.0f / NPG));
}

// ---------------- lin1: z[16,2176] @ W[2176,128], split over i-dimension ----------------
__global__ void k_lin1(const float* __restrict__ H, const int* __restrict__ base,
                       const float* __restrict__ W1) {
    __shared__ float zsh[BB * 128];   // this block's z slice
    int t = threadIdx.x;
    int i0 = blockIdx.x * 128;        // 17 blocks cover i in [0,2176)

    for (int idx = t; idx < BB * 128; idx += 128) {
        int g = idx >> 7, ii = idx & 127;
        int i = i0 + ii;
        float v;
        if (i < KK * DD) {            // selective gather part x_s
            int k = i >> 7, d = i & 127;
            int bn = base[g * KK + k];
            v = (bn > 0) ? H[((size_t)g * NPG + bn) * DD + d] : 0.f;
        } else {                      // global pool part x_g
            v = g_xg[g * DD + (i - KK * DD)];
        }
        zsh[idx] = v;
    }
    __syncthreads();

    float acc[BB];
#pragma unroll
    for (int g = 0; g < BB; g++) acc[g] = 0.f;
    for (int ii = 0; ii < 128; ii++) {
        float w = W1[(size_t)(i0 + ii) * DD + t];
#pragma unroll
        for (int g = 0; g < BB; g++) acc[g] = fmaf(zsh[g * 128 + ii], w, acc[g]);
    }
#pragma unroll
    for (int g = 0; g < BB; g++) atomicAdd(&g_z1[g * DD + t], acc[g]);
}

// ---------------- final: relu(z1 + b) concat cond -> lin2 -> out[16,2] ----------------
__global__ void k_final(const float* __restrict__ lin1_b, const float* __restrict__ cond,
                        const float* __restrict__ W2, const float* __restrict__ b2,
                        float* __restrict__ out) {
    int t = threadIdx.x;
    if (t >= BB * NC) return;
    int g = t >> 1, c = t & 1;
    float acc = b2[c];
    for (int j = 0; j < DD; j++) {
        float z = fmaxf(g_z1[g * DD + j] + lin1_b[j], 0.f);
        acc = fmaf(z, W2[j * NC + c], acc);
    }
    for (int j = 0; j < DCOND; j++)
        acc = fmaf(cond[g * DCOND + j], W2[(DD + j) * NC + c], acc);
    out[g * NC + c] = acc;
}

// ---------------- launch ----------------
extern "C" void kernel_launch(void* const* d_in, const int* in_sizes, int n_in,
                              void* d_out, int out_size) {
    const float* x      = (const float*)d_in[0];
    const int*   ei     = (const int*)d_in[1];
    const int*   src    = ei;
    const int*   dst    = ei + EE;
    const int*   base   = (const int*)d_in[3];
    const float* cond   = (const float*)d_in[4];
    const float* W[5]   = {(const float*)d_in[5], (const float*)d_in[7],
                           (const float*)d_in[9], (const float*)d_in[11],
                           (const float*)d_in[13]};
    const float* bias[5] = {(const float*)d_in[6], (const float*)d_in[8],
                            (const float*)d_in[10], (const float*)d_in[12],
                            (const float*)d_in[14]};
    const float* lin1_W = (const float*)d_in[15];
    const float* lin1_b = (const float*)d_in[16];
    const float* lin2_W = (const float*)d_in[17];
    const float* lin2_b = (const float*)d_in[18];
    float* out = (float*)d_out;

    // 96 KB dynamic SMEM for the GEMM (idempotent; capture-safe)
    cudaFuncSetAttribute(k_gemm, cudaFuncAttributeMaxDynamicSharedMemorySize, 98304);

    void *pa, *pb;
    cudaGetSymbolAddress(&pa, g_bufA);
    cudaGetSymbolAddress(&pb, g_bufB);
    float* A  = (float*)pa;
    float* Bv = (float*)pb;

    // CSR build (recomputed every launch; deterministic work)
    k_zero<<<NBLK, 256>>>();
    k_hist<<<EE / 256, 256>>>(dst);
    k_scan1<<<NBLK, 256>>>();
    k_scan2<<<1, 256>>>();
    k_scan3<<<NBLK, 256>>>();
    k_scatter<<<EE / 256, 256>>>(src, dst);

    // 5 GCN layers (ping-pong between g_bufA / g_bufB)
    k_gemm<<<NN / 64, 256, 98304>>>(x, W[0], Bv);
    k_agg<<<NN / 4, 128>>>(Bv, A, bias[0], 1);
    for (int l = 1; l < 5; l++) {
        k_gemm<<<NN / 64, 256, 98304>>>(A, W[l], Bv);
        k_agg<<<NN / 4, 128>>>(Bv, A, bias[l], (l < 4) ? 1 : 0);
    }

    // readout
    k_pool<<<dim3(BB, 8), 128>>>(A);
    k_lin1<<<17, 128>>>(A, base, lin1_W);
    k_final<<<1, 32>>>(lin1_b, cond, lin2_W, lin2_b, out);
}